// round 8
// baseline (speedup 1.0000x reference)
#include <cuda_runtime.h>
#include <cuda_bf16.h>
#include <cstdint>

#define NN   50000
#define ECNT 800000

// ===================== helpers =============================================
__device__ __forceinline__ uint32_t smem_to_u32(const void* p) {
    uint32_t a;
    asm("{ .reg .u64 t; cvta.to.shared.u64 t, %1; cvt.u32.u64 %0, t; }"
        : "=r"(a) : "l"(p));
    return a;
}
__device__ __forceinline__ void ldsm_x4(uint32_t* r, uint32_t addr) {
    asm volatile("ldmatrix.sync.aligned.m8n8.x4.shared.b16 {%0,%1,%2,%3}, [%4];"
        : "=r"(r[0]), "=r"(r[1]), "=r"(r[2]), "=r"(r[3]) : "r"(addr));
}
__device__ __forceinline__ void mma_bf16(float* c, const uint32_t* a,
                                         uint32_t b0, uint32_t b1) {
    asm volatile("mma.sync.aligned.m16n8k16.row.col.f32.bf16.bf16.f32 "
        "{%0,%1,%2,%3}, {%4,%5,%6,%7}, {%8,%9}, {%0,%1,%2,%3};"
        : "+f"(c[0]), "+f"(c[1]), "+f"(c[2]), "+f"(c[3])
        : "r"(a[0]), "r"(a[1]), "r"(a[2]), "r"(a[3]), "r"(b0), "r"(b1));
}
__device__ __forceinline__ void cp16(uint32_t dst, const void* src) {
    asm volatile("cp.async.cg.shared.global [%0], [%1], 16;"
                 :: "r"(dst), "l"(src) : "memory");
}
__device__ __forceinline__ void cp_commit() {
    asm volatile("cp.async.commit_group;" ::: "memory");
}
template<int N>
__device__ __forceinline__ void cp_wait() {
    asm volatile("cp.async.wait_group %0;" :: "n"(N) : "memory");
}
__device__ __forceinline__ uint32_t split_pack_hi(float a, float b,
                                                  uint32_t& lo_pack) {
    __nv_bfloat16 h0 = __float2bfloat16(a);
    __nv_bfloat16 h1 = __float2bfloat16(b);
    __nv_bfloat16 l0 = __float2bfloat16(a - __bfloat162float(h0));
    __nv_bfloat16 l1 = __float2bfloat16(b - __bfloat162float(h1));
    lo_pack = (uint32_t)__bfloat16_as_ushort(l0)
            | ((uint32_t)__bfloat16_as_ushort(l1) << 16);
    return (uint32_t)__bfloat16_as_ushort(h0)
         | ((uint32_t)__bfloat16_as_ushort(h1) << 16);
}

// ---------------- scratch (device globals; no allocation allowed) ----------
__device__ int   g_degi[NN];
__device__ int   g_off [NN];
__device__ int   g_fill[NN];
__device__ float g_dinv[NN];
__device__ int   g_csrc[ECNT];
__device__ float g_h2  [(size_t)NN * 64];
__device__ __nv_bfloat16 g_axh[(size_t)NN * 128], g_axl[(size_t)NN * 128];
__device__ __nv_bfloat16 g_h1h[(size_t)NN * 256], g_h1l[(size_t)NN * 256];
__device__ __nv_bfloat16 g_zh [(size_t)NN * 64],  g_zl [(size_t)NN * 64];
__device__ __nv_bfloat16 g_dh [(size_t)NN * 256], g_dl [(size_t)NN * 256];
__device__ __nv_bfloat16 g_w1h[256 * 128],  g_w1l[256 * 128];   // [N][K]
__device__ __nv_bfloat16 g_w2h[64 * 256],   g_w2l[64 * 256];
__device__ __nv_bfloat16 g_wd1h[256 * 64],  g_wd1l[256 * 64];
__device__ __nv_bfloat16 g_wd2h[128 * 256], g_wd2l[128 * 256];

// ---------------- prep: weight splits (transposed) + degi zero -------------
__device__ __forceinline__ void splitw(const float* W, __nv_bfloat16* th,
                                       __nv_bfloat16* tl, int i, int K, int N) {
    int k = i / N, n = i % N;
    float v = W[i];
    __nv_bfloat16 h = __float2bfloat16(v);
    th[n * K + k] = h;
    tl[n * K + k] = __float2bfloat16(v - __bfloat162float(h));
}
__global__ void k_prep(const float* __restrict__ W1, const float* __restrict__ W2,
                       const float* __restrict__ Wd1, const float* __restrict__ Wd2)
{
    int i = blockIdx.x * 256 + threadIdx.x;
    if (i < 32768) {
        splitw(W1, g_w1h, g_w1l, i, 128, 256);
    } else if (i < 49152) {
        splitw(W2, g_w2h, g_w2l, i - 32768, 256, 64);
    } else if (i < 65536) {
        splitw(Wd1, g_wd1h, g_wd1l, i - 49152, 64, 256);
    } else if (i < 98304) {
        splitw(Wd2, g_wd2h, g_wd2l, i - 65536, 256, 128);
    } else {
        int n = i - 98304;
        if (n < NN) g_degi[n] = 0;
    }
}
__global__ void k_deg_count(const int* __restrict__ dst) {
    int e = blockIdx.x * 256 + threadIdx.x;
    if (e < ECNT) atomicAdd(&g_degi[dst[e]], 1);
}

// ---------------- single-block scan: offsets, dinv, fill=0 -----------------
__global__ void k_scan() {
    const int T = 1024;
    const int CH = (NN + T - 1) / T;        // 49
    __shared__ int part[T];
    int t = threadIdx.x;
    int s0 = t * CH;
    int s1 = (s0 + CH < NN) ? s0 + CH : NN;
    int sum = 0;
    for (int i = s0; i < s1; i++) sum += g_degi[i];
    part[t] = sum;
    __syncthreads();
    for (int d = 1; d < T; d <<= 1) {
        int v = (t >= d) ? part[t - d] : 0;
        __syncthreads();
        part[t] += v;
        __syncthreads();
    }
    int run = (t > 0) ? part[t - 1] : 0;
    for (int i = s0; i < s1; i++) {
        int c = g_degi[i];
        g_off[i]  = run;
        g_fill[i] = 0;
        g_dinv[i] = rsqrtf(1.0f + (float)c);   // self-loop included
        run += c;
    }
}

// ---------------- bucket edges into CSR (src only) -------------------------
__global__ void k_bucket(const int* __restrict__ src, const int* __restrict__ dst) {
    int e = blockIdx.x * 256 + threadIdx.x;
    if (e >= ECNT) return;
    int s = src[e], d = dst[e];
    int pos = g_off[d] + atomicAdd(&g_fill[d], 1);
    g_csrc[pos] = s;
}

// ------- layer-1 aggregate+split: one 128-thread block per node ------------
// out(hi/lo bf16) = split( x[n]*dinv[n]^2 + sum_e x[src_e]*dinv[src_e]*dinv[n] )
__global__ void __launch_bounds__(128)
k_agg1(const float* __restrict__ x,
       __nv_bfloat16* __restrict__ oh, __nv_bfloat16* __restrict__ ol)
{
    __shared__ int   ss[128];
    __shared__ float sn[128];
    int node = blockIdx.x;
    int ch = threadIdx.x;
    float di = g_dinv[node];
    float acc = x[(size_t)node * 128 + ch] * di * di;
    int b = g_off[node];
    int n = g_degi[node];
    for (int base = 0; base < n; base += 128) {
        int m = n - base; if (m > 128) m = 128;
        if (ch < m) {
            int s = g_csrc[b + base + ch];
            ss[ch] = s;
            sn[ch] = g_dinv[s] * di;
        }
        __syncthreads();
        int j = 0;
        for (; j + 8 <= m; j += 8) {
            int s0 = ss[j],     s1 = ss[j + 1], s2 = ss[j + 2], s3 = ss[j + 3];
            int s4 = ss[j + 4], s5 = ss[j + 5], s6 = ss[j + 6], s7 = ss[j + 7];
            float m0 = sn[j],     m1 = sn[j + 1], m2 = sn[j + 2], m3 = sn[j + 3];
            float m4 = sn[j + 4], m5 = sn[j + 5], m6 = sn[j + 6], m7 = sn[j + 7];
            float v0 = __ldg(&x[(size_t)s0 * 128 + ch]);
            float v1 = __ldg(&x[(size_t)s1 * 128 + ch]);
            float v2 = __ldg(&x[(size_t)s2 * 128 + ch]);
            float v3 = __ldg(&x[(size_t)s3 * 128 + ch]);
            float v4 = __ldg(&x[(size_t)s4 * 128 + ch]);
            float v5 = __ldg(&x[(size_t)s5 * 128 + ch]);
            float v6 = __ldg(&x[(size_t)s6 * 128 + ch]);
            float v7 = __ldg(&x[(size_t)s7 * 128 + ch]);
            acc = fmaf(v0, m0, acc); acc = fmaf(v1, m1, acc);
            acc = fmaf(v2, m2, acc); acc = fmaf(v3, m3, acc);
            acc = fmaf(v4, m4, acc); acc = fmaf(v5, m5, acc);
            acc = fmaf(v6, m6, acc); acc = fmaf(v7, m7, acc);
        }
        if (j + 4 <= m) {
            int s0 = ss[j], s1 = ss[j + 1], s2 = ss[j + 2], s3 = ss[j + 3];
            float m0 = sn[j], m1 = sn[j + 1], m2 = sn[j + 2], m3 = sn[j + 3];
            float v0 = __ldg(&x[(size_t)s0 * 128 + ch]);
            float v1 = __ldg(&x[(size_t)s1 * 128 + ch]);
            float v2 = __ldg(&x[(size_t)s2 * 128 + ch]);
            float v3 = __ldg(&x[(size_t)s3 * 128 + ch]);
            acc = fmaf(v0, m0, acc); acc = fmaf(v1, m1, acc);
            acc = fmaf(v2, m2, acc); acc = fmaf(v3, m3, acc);
            j += 4;
        }
        for (; j < m; j++)
            acc = fmaf(__ldg(&x[(size_t)ss[j] * 128 + ch]), sn[j], acc);
        __syncthreads();
    }
    __nv_bfloat16 h = __float2bfloat16(acc);
    oh[(size_t)node * 128 + ch] = h;
    ol[(size_t)node * 128 + ch] = __float2bfloat16(acc - __bfloat162float(h));
}

// ------- layer-2 aggregate+bias+split: one warp per node (C=64) ------------
__global__ void __launch_bounds__(256)
k_agg2(const float* __restrict__ h2, const float* __restrict__ bias,
       __nv_bfloat16* __restrict__ oh, __nv_bfloat16* __restrict__ ol)
{
    int node = blockIdx.x * 8 + (threadIdx.x >> 5);
    if (node >= NN) return;
    int lane = threadIdx.x & 31;
    float di = g_dinv[node];
    float s2 = di * di;
    float2 v = *(const float2*)&h2[(size_t)node * 64 + lane * 2];
    float2 bv = *(const float2*)&bias[lane * 2];
    float ax = fmaf(v.x, s2, bv.x);
    float ay = fmaf(v.y, s2, bv.y);
    int b = g_off[node];
    int n = g_degi[node];
    for (int base = 0; base < n; base += 32) {
        int m = n - base; if (m > 32) m = 32;
        int sl = 0; float nl = 0.f;
        if (lane < m) {
            sl = __ldg(&g_csrc[b + base + lane]);
            nl = __ldg(&g_dinv[sl]) * di;
        }
        int j = 0;
        for (; j + 4 <= m; j += 4) {
            int   s0 = __shfl_sync(0xFFFFFFFF, sl, j);
            int   s1 = __shfl_sync(0xFFFFFFFF, sl, j + 1);
            int   sq = __shfl_sync(0xFFFFFFFF, sl, j + 2);
            int   s3 = __shfl_sync(0xFFFFFFFF, sl, j + 3);
            float n0 = __shfl_sync(0xFFFFFFFF, nl, j);
            float n1 = __shfl_sync(0xFFFFFFFF, nl, j + 1);
            float n2 = __shfl_sync(0xFFFFFFFF, nl, j + 2);
            float n3 = __shfl_sync(0xFFFFFFFF, nl, j + 3);
            float2 w0 = *(const float2*)&h2[(size_t)s0 * 64 + lane * 2];
            float2 w1 = *(const float2*)&h2[(size_t)s1 * 64 + lane * 2];
            float2 w2 = *(const float2*)&h2[(size_t)sq * 64 + lane * 2];
            float2 w3 = *(const float2*)&h2[(size_t)s3 * 64 + lane * 2];
            ax = fmaf(w0.x, n0, ax); ay = fmaf(w0.y, n0, ay);
            ax = fmaf(w1.x, n1, ax); ay = fmaf(w1.y, n1, ay);
            ax = fmaf(w2.x, n2, ax); ay = fmaf(w2.y, n2, ay);
            ax = fmaf(w3.x, n3, ax); ay = fmaf(w3.y, n3, ay);
        }
        for (; j < m; j++) {
            int   s0 = __shfl_sync(0xFFFFFFFF, sl, j);
            float n0 = __shfl_sync(0xFFFFFFFF, nl, j);
            float2 w = *(const float2*)&h2[(size_t)s0 * 64 + lane * 2];
            ax = fmaf(w.x, n0, ax); ay = fmaf(w.y, n0, ay);
        }
    }
    uint32_t lp;
    uint32_t hp = split_pack_hi(ax, ay, lp);
    *(uint32_t*)&oh[(size_t)node * 64 + lane * 2] = hp;
    *(uint32_t*)&ol[(size_t)node * 64 + lane * 2] = lp;
}

// ============ bf16x3 tensor-core GEMM, 2-stage cp.async pipeline ===========
template<int KTOT, int NTOT, bool BIAS, bool RELU, bool SPLIT>
__global__ void __launch_bounds__(256, 2)
k_gemm_bf(const __nv_bfloat16* __restrict__ Ah, const __nv_bfloat16* __restrict__ Al,
          const __nv_bfloat16* __restrict__ Bh, const __nv_bfloat16* __restrict__ Bl,
          const float* __restrict__ bias, float* __restrict__ Cf,
          __nv_bfloat16* __restrict__ Ch, __nv_bfloat16* __restrict__ Cl)
{
    constexpr int M  = NN;
    constexpr int TK = 64;
    constexpr int ST = 72;
    constexpr int NSTAGE = KTOT / TK;
    constexpr int A_SZ = 128 * ST * 2;
    constexpr int B_SZ = 64 * ST * 2;
    constexpr int STG  = 2 * A_SZ + 2 * B_SZ;
    constexpr int PIPE = (NSTAGE > 1) ? 2 : 1;

    extern __shared__ char smem[];
    uint32_t sb = smem_to_u32(smem);
    int tid = threadIdx.x, l = tid & 31, wid = tid >> 5;
    int wm = wid >> 1, wn = wid & 1;
    int bm = blockIdx.y * 128, bn = blockIdx.x * 64;

    float acc[2][4][4];
#pragma unroll
    for (int mt = 0; mt < 2; mt++)
#pragma unroll
        for (int nt = 0; nt < 4; nt++)
#pragma unroll
            for (int j = 0; j < 4; j++) acc[mt][nt][j] = 0.0f;

    int r8 = (l & 7) + ((l >> 3) & 1) * 8;
    int c8 = (l >> 4) * 8;
    uint32_t aAH[2], aAL[2], aBH[2], aBL[2];
#pragma unroll
    for (int mt = 0; mt < 2; mt++) {
        uint32_t o = (uint32_t)(((wm * 32 + mt * 16 + r8) * ST + c8) * 2);
        aAH[mt] = sb + o;
        aAL[mt] = sb + A_SZ + o;
    }
#pragma unroll
    for (int nb = 0; nb < 2; nb++) {
        uint32_t o = (uint32_t)(((wn * 32 + nb * 16 + r8) * ST + c8) * 2);
        aBH[nb] = sb + 2 * A_SZ + o;
        aBL[nb] = sb + 2 * A_SZ + B_SZ + o;
    }

    auto load_stage = [&](int s, int buf) {
        int k0 = s * TK;
        uint32_t base = sb + buf * STG;
#pragma unroll
        for (int it = 0; it < 8; it++) {
            int i   = tid + it * 256;
            int row = i >> 4;
            int sub = i & 15;
            int arr = sub >> 3;
            int ch  = sub & 7;
            int gr  = bm + row;
            if (gr < M) {
                const __nv_bfloat16* src =
                    (arr ? Al : Ah) + (size_t)gr * KTOT + k0 + ch * 8;
                cp16(base + arr * A_SZ + row * (ST * 2) + ch * 16, src);
            }
        }
#pragma unroll
        for (int it = 0; it < 4; it++) {
            int i   = tid + it * 256;
            int n   = i >> 4;
            int sub = i & 15;
            int arr = sub >> 3;
            int ch  = sub & 7;
            const __nv_bfloat16* src =
                (arr ? Bl : Bh) + (size_t)(bn + n) * KTOT + k0 + ch * 8;
            cp16(base + 2 * A_SZ + arr * B_SZ + n * (ST * 2) + ch * 16, src);
        }
        cp_commit();
    };

    load_stage(0, 0);

    for (int s = 0; s < NSTAGE; s++) {
        int buf = (PIPE == 2) ? (s & 1) : 0;
        if (PIPE == 2 && s + 1 < NSTAGE) load_stage(s + 1, buf ^ 1);
        if (PIPE == 2 && s + 1 < NSTAGE) cp_wait<1>(); else cp_wait<0>();
        __syncthreads();

        uint32_t bo = buf * STG;
#pragma unroll
        for (int ks = 0; ks < TK / 16; ks++) {
            uint32_t koff = bo + ks * 32;
            uint32_t ah0[4], ah1[4], al0[4], al1[4];
            uint32_t bh0[4], bh1[4], bl0[4], bl1[4];
            ldsm_x4(ah0, aAH[0] + koff);
            ldsm_x4(ah1, aAH[1] + koff);
            ldsm_x4(al0, aAL[0] + koff);
            ldsm_x4(al1, aAL[1] + koff);
            ldsm_x4(bh0, aBH[0] + koff);
            ldsm_x4(bh1, aBH[1] + koff);
            ldsm_x4(bl0, aBL[0] + koff);
            ldsm_x4(bl1, aBL[1] + koff);
#pragma unroll
            for (int mt = 0; mt < 2; mt++) {
                const uint32_t* a_h = mt ? ah1 : ah0;
                const uint32_t* a_l = mt ? al1 : al0;
#pragma unroll
                for (int nt = 0; nt < 4; nt++) {
                    const uint32_t* b_h = (nt >> 1) ? bh1 : bh0;
                    const uint32_t* b_l = (nt >> 1) ? bl1 : bl0;
                    int sub = nt & 1;
                    mma_bf16(acc[mt][nt], a_h, b_h[sub], b_h[sub + 2]);
                    mma_bf16(acc[mt][nt], a_h, b_l[sub], b_l[sub + 2]);
                    mma_bf16(acc[mt][nt], a_l, b_h[sub], b_h[sub + 2]);
                }
            }
        }
        __syncthreads();
    }

    int g = l >> 2, tg = l & 3;
#pragma unroll
    for (int mt = 0; mt < 2; mt++) {
        int row0 = bm + wm * 32 + mt * 16 + g;
#pragma unroll
        for (int nt = 0; nt < 4; nt++) {
            int col = bn + wn * 32 + nt * 8 + tg * 2;
            float bx = 0.f, by = 0.f;
            if (BIAS) {
                float2 bv = *(const float2*)&bias[col];
                bx = bv.x; by = bv.y;
            }
            float2 o0 = make_float2(acc[mt][nt][0] + bx, acc[mt][nt][1] + by);
            float2 o1 = make_float2(acc[mt][nt][2] + bx, acc[mt][nt][3] + by);
            if (RELU) {
                o0.x = fmaxf(o0.x, 0.f); o0.y = fmaxf(o0.y, 0.f);
                o1.x = fmaxf(o1.x, 0.f); o1.y = fmaxf(o1.y, 0.f);
            }
            if (SPLIT) {
                uint32_t lp;
                if (row0 < M) {
                    uint32_t hp = split_pack_hi(o0.x, o0.y, lp);
                    *(uint32_t*)&Ch[(size_t)row0 * NTOT + col] = hp;
                    *(uint32_t*)&Cl[(size_t)row0 * NTOT + col] = lp;
                }
                if (row0 + 8 < M) {
                    uint32_t hp = split_pack_hi(o1.x, o1.y, lp);
                    *(uint32_t*)&Ch[(size_t)(row0 + 8) * NTOT + col] = hp;
                    *(uint32_t*)&Cl[(size_t)(row0 + 8) * NTOT + col] = lp;
                }
            } else {
                if (row0 < M)
                    *(float2*)&Cf[(size_t)row0 * NTOT + col] = o0;
                if (row0 + 8 < M)
                    *(float2*)&Cf[(size_t)(row0 + 8) * NTOT + col] = o1;
            }
        }
    }
}

// ---------------- launch ---------------------------------------------------
extern "C" void kernel_launch(void* const* d_in, const int* in_sizes, int n_in,
                              void* d_out, int out_size)
{
    const float* x   = (const float*)d_in[0];
    const int*   ei  = (const int*)  d_in[1];
    const float* W1  = (const float*)d_in[2];
    const float* b1  = (const float*)d_in[3];
    const float* W2  = (const float*)d_in[4];
    const float* b2  = (const float*)d_in[5];
    const float* Wd1 = (const float*)d_in[6];
    const float* bd1 = (const float*)d_in[7];
    const float* Wd2 = (const float*)d_in[8];
    const float* bd2 = (const float*)d_in[9];
    float* out = (float*)d_out;

    const int* srcp = ei;
    const int* dstp = ei + ECNT;

    float* p_h2;
    cudaGetSymbolAddress((void**)&p_h2, g_h2);
    __nv_bfloat16 *p_axh, *p_axl, *p_h1h, *p_h1l, *p_zh, *p_zl, *p_dh, *p_dl;
    __nv_bfloat16 *p_w1h, *p_w1l, *p_w2h, *p_w2l, *p_wd1h, *p_wd1l, *p_wd2h, *p_wd2l;
    cudaGetSymbolAddress((void**)&p_axh, g_axh);
    cudaGetSymbolAddress((void**)&p_axl, g_axl);
    cudaGetSymbolAddress((void**)&p_h1h, g_h1h);
    cudaGetSymbolAddress((void**)&p_h1l, g_h1l);
    cudaGetSymbolAddress((void**)&p_zh,  g_zh);
    cudaGetSymbolAddress((void**)&p_zl,  g_zl);
    cudaGetSymbolAddress((void**)&p_dh,  g_dh);
    cudaGetSymbolAddress((void**)&p_dl,  g_dl);
    cudaGetSymbolAddress((void**)&p_w1h, g_w1h);
    cudaGetSymbolAddress((void**)&p_w1l, g_w1l);
    cudaGetSymbolAddress((void**)&p_w2h, g_w2h);
    cudaGetSymbolAddress((void**)&p_w2l, g_w2l);
    cudaGetSymbolAddress((void**)&p_wd1h, g_wd1h);
    cudaGetSymbolAddress((void**)&p_wd1l, g_wd1l);
    cudaGetSymbolAddress((void**)&p_wd2h, g_wd2h);
    cudaGetSymbolAddress((void**)&p_wd2l, g_wd2l);

    const int STG = 2 * (128 * 72 * 2) + 2 * (64 * 72 * 2);  // 55296
    cudaFuncSetAttribute((const void*)k_gemm_bf<128, 256, true,  true,  true >,
                         cudaFuncAttributeMaxDynamicSharedMemorySize, 2 * STG);
    cudaFuncSetAttribute((const void*)k_gemm_bf<256, 64,  false, false, false>,
                         cudaFuncAttributeMaxDynamicSharedMemorySize, 2 * STG);
    cudaFuncSetAttribute((const void*)k_gemm_bf<64,  256, true,  true,  true >,
                         cudaFuncAttributeMaxDynamicSharedMemorySize, STG);
    cudaFuncSetAttribute((const void*)k_gemm_bf<256, 128, true,  false, false>,
                         cudaFuncAttributeMaxDynamicSharedMemorySize, 2 * STG);

    // --- prep + CSR build
    k_prep<<<(98304 + NN + 255) / 256, 256>>>(W1, W2, Wd1, Wd2);
    k_deg_count<<<(ECNT + 255) / 256, 256>>>(dstp);
    k_scan<<<1, 1024>>>();
    k_bucket<<<(ECNT + 255) / 256, 256>>>(srcp, dstp);

    const int MB = (NN + 127) / 128;   // 391 row-blocks

    // --- layer 1: aggregate x (CSR gather) -> bf16 split; GEMM
    k_agg1<<<NN, 128>>>(x, p_axh, p_axl);
    k_gemm_bf<128, 256, true, true, true><<<dim3(4, MB), 256, 2 * STG>>>(
        p_axh, p_axl, p_w1h, p_w1l, b1, nullptr, p_h1h, p_h1l);

    // --- layer 2: h2 = h1 @ W2 [fp32]; aggregate + b2 -> bf16 split
    k_gemm_bf<256, 64, false, false, false><<<dim3(1, MB), 256, 2 * STG>>>(
        p_h1h, p_h1l, p_w2h, p_w2l, nullptr, p_h2, nullptr, nullptr);
    k_agg2<<<(NN + 7) / 8, 256>>>(p_h2, b2, p_zh, p_zl);

    // --- decoder
    k_gemm_bf<64, 256, true, true, true><<<dim3(4, MB), 256, STG>>>(
        p_zh, p_zl, p_wd1h, p_wd1l, bd1, nullptr, p_dh, p_dl);
    k_gemm_bf<256, 128, true, false, false><<<dim3(2, MB), 256, 2 * STG>>>(
        p_dh, p_dl, p_wd2h, p_wd2l, bd2, out, nullptr, nullptr);
}

// round 9
// speedup vs baseline: 1.1694x; 1.1694x over previous
#include <cuda_runtime.h>
#include <cuda_bf16.h>
#include <cstdint>

#define NN   50000
#define ECNT 800000

// ===================== helpers =============================================
__device__ __forceinline__ uint32_t smem_to_u32(const void* p) {
    uint32_t a;
    asm("{ .reg .u64 t; cvta.to.shared.u64 t, %1; cvt.u32.u64 %0, t; }"
        : "=r"(a) : "l"(p));
    return a;
}
__device__ __forceinline__ void ldsm_x4(uint32_t* r, uint32_t addr) {
    asm volatile("ldmatrix.sync.aligned.m8n8.x4.shared.b16 {%0,%1,%2,%3}, [%4];"
        : "=r"(r[0]), "=r"(r[1]), "=r"(r[2]), "=r"(r[3]) : "r"(addr));
}
__device__ __forceinline__ void mma_bf16(float* c, const uint32_t* a,
                                         uint32_t b0, uint32_t b1) {
    asm volatile("mma.sync.aligned.m16n8k16.row.col.f32.bf16.bf16.f32 "
        "{%0,%1,%2,%3}, {%4,%5,%6,%7}, {%8,%9}, {%0,%1,%2,%3};"
        : "+f"(c[0]), "+f"(c[1]), "+f"(c[2]), "+f"(c[3])
        : "r"(a[0]), "r"(a[1]), "r"(a[2]), "r"(a[3]), "r"(b0), "r"(b1));
}
__device__ __forceinline__ void cp16(uint32_t dst, const void* src) {
    asm volatile("cp.async.cg.shared.global [%0], [%1], 16;"
                 :: "r"(dst), "l"(src) : "memory");
}
__device__ __forceinline__ void cp_commit() {
    asm volatile("cp.async.commit_group;" ::: "memory");
}
template<int N>
__device__ __forceinline__ void cp_wait() {
    asm volatile("cp.async.wait_group %0;" :: "n"(N) : "memory");
}
__device__ __forceinline__ uint32_t split_pack_hi(float a, float b,
                                                  uint32_t& lo_pack) {
    __nv_bfloat16 h0 = __float2bfloat16(a);
    __nv_bfloat16 h1 = __float2bfloat16(b);
    __nv_bfloat16 l0 = __float2bfloat16(a - __bfloat162float(h0));
    __nv_bfloat16 l1 = __float2bfloat16(b - __bfloat162float(h1));
    lo_pack = (uint32_t)__bfloat16_as_ushort(l0)
            | ((uint32_t)__bfloat16_as_ushort(l1) << 16);
    return (uint32_t)__bfloat16_as_ushort(h0)
         | ((uint32_t)__bfloat16_as_ushort(h1) << 16);
}

// ---------------- scratch (device globals; no allocation allowed) ----------
__device__ float g_deg [NN];
__device__ float g_dinv[NN];
__device__ float g_aggx[(size_t)NN * 128];
__device__ float g_h2  [(size_t)NN * 64];
__device__ float g_z   [(size_t)NN * 64];
__device__ __nv_bfloat16 g_axh[(size_t)NN * 128], g_axl[(size_t)NN * 128];
__device__ __nv_bfloat16 g_h1h[(size_t)NN * 256], g_h1l[(size_t)NN * 256];
__device__ __nv_bfloat16 g_zh [(size_t)NN * 64],  g_zl [(size_t)NN * 64];
__device__ __nv_bfloat16 g_dh [(size_t)NN * 256], g_dl [(size_t)NN * 256];
__device__ __nv_bfloat16 g_w1h[256 * 128],  g_w1l[256 * 128];   // [N][K]
__device__ __nv_bfloat16 g_w2h[64 * 256],   g_w2l[64 * 256];
__device__ __nv_bfloat16 g_wd1h[256 * 64],  g_wd1l[256 * 64];
__device__ __nv_bfloat16 g_wd2h[128 * 256], g_wd2l[128 * 256];

// ---------------- prep: all 4 weight splits (transposed) + deg init --------
__device__ __forceinline__ void splitw(const float* W, __nv_bfloat16* th,
                                       __nv_bfloat16* tl, int i, int K, int N) {
    int k = i / N, n = i % N;
    float v = W[i];
    __nv_bfloat16 h = __float2bfloat16(v);
    th[n * K + k] = h;
    tl[n * K + k] = __float2bfloat16(v - __bfloat162float(h));
}
__global__ void k_prep(const float* __restrict__ W1, const float* __restrict__ W2,
                       const float* __restrict__ Wd1, const float* __restrict__ Wd2)
{
    int i = blockIdx.x * 256 + threadIdx.x;
    if (i < 32768) {
        splitw(W1, g_w1h, g_w1l, i, 128, 256);
    } else if (i < 49152) {
        splitw(W2, g_w2h, g_w2l, i - 32768, 256, 64);
    } else if (i < 65536) {
        splitw(Wd1, g_wd1h, g_wd1l, i - 49152, 64, 256);
    } else if (i < 98304) {
        splitw(Wd2, g_wd2h, g_wd2l, i - 65536, 256, 128);
    } else {
        int n = i - 98304;
        if (n < NN) g_deg[n] = 1.0f;     // self-loop contributes 1
    }
}
__global__ void k_deg_count(const int* __restrict__ dst) {
    int e = blockIdx.x * 256 + threadIdx.x;
    if (e < ECNT) atomicAdd(&g_deg[dst[e]], 1.0f);
}

// ---------------- fp32 -> bf16 hi/lo split (flat, vectorized) --------------
__global__ void k_split(const float* __restrict__ in,
                        __nv_bfloat16* __restrict__ oh,
                        __nv_bfloat16* __restrict__ ol, int n4)
{
    int i = blockIdx.x * 256 + threadIdx.x;
    if (i >= n4) return;
    float4 v = ((const float4*)in)[i];
    uint32_t l0, l1;
    uint32_t h0 = split_pack_hi(v.x, v.y, l0);
    uint32_t h1 = split_pack_hi(v.z, v.w, l1);
    ((uint2*)oh)[i] = make_uint2(h0, h1);
    ((uint2*)ol)[i] = make_uint2(l0, l1);
}

// ============ bf16x3 tensor-core GEMM, 2-stage cp.async pipeline ===========
// CTA tile 128x64, 8 warps (4m x 2n), warp 32x32 = 2x4 m16n8k16 tiles.
// acc += Ah*Bh + Ah*Bl + Al*Bh (fp32).
// Output modes: fp32 (Cf) | hi/lo-split bf16 (Ch,Cl) | ZINIT: Cf=h2 AND
// g_z = h2*dinv^2 + bias (fused layer-2 aggregation init).
template<int KTOT, int NTOT, bool BIAS, bool RELU, bool SPLIT, bool ZINIT>
__global__ void __launch_bounds__(256, 2)
k_gemm_bf(const __nv_bfloat16* __restrict__ Ah, const __nv_bfloat16* __restrict__ Al,
          const __nv_bfloat16* __restrict__ Bh, const __nv_bfloat16* __restrict__ Bl,
          const float* __restrict__ bias, float* __restrict__ Cf,
          __nv_bfloat16* __restrict__ Ch, __nv_bfloat16* __restrict__ Cl)
{
    constexpr int M  = NN;
    constexpr int TK = 64;
    constexpr int ST = 72;
    constexpr int NSTAGE = KTOT / TK;
    constexpr int A_SZ = 128 * ST * 2;
    constexpr int B_SZ = 64 * ST * 2;
    constexpr int STG  = 2 * A_SZ + 2 * B_SZ;
    constexpr int PIPE = (NSTAGE > 1) ? 2 : 1;

    extern __shared__ char smem[];
    uint32_t sb = smem_to_u32(smem);
    int tid = threadIdx.x, l = tid & 31, wid = tid >> 5;
    int wm = wid >> 1, wn = wid & 1;
    int bm = blockIdx.y * 128, bn = blockIdx.x * 64;

    float acc[2][4][4];
#pragma unroll
    for (int mt = 0; mt < 2; mt++)
#pragma unroll
        for (int nt = 0; nt < 4; nt++)
#pragma unroll
            for (int j = 0; j < 4; j++) acc[mt][nt][j] = 0.0f;

    int r8 = (l & 7) + ((l >> 3) & 1) * 8;
    int c8 = (l >> 4) * 8;
    uint32_t aAH[2], aAL[2], aBH[2], aBL[2];
#pragma unroll
    for (int mt = 0; mt < 2; mt++) {
        uint32_t o = (uint32_t)(((wm * 32 + mt * 16 + r8) * ST + c8) * 2);
        aAH[mt] = sb + o;
        aAL[mt] = sb + A_SZ + o;
    }
#pragma unroll
    for (int nb = 0; nb < 2; nb++) {
        uint32_t o = (uint32_t)(((wn * 32 + nb * 16 + r8) * ST + c8) * 2);
        aBH[nb] = sb + 2 * A_SZ + o;
        aBL[nb] = sb + 2 * A_SZ + B_SZ + o;
    }

    auto load_stage = [&](int s, int buf) {
        int k0 = s * TK;
        uint32_t base = sb + buf * STG;
#pragma unroll
        for (int it = 0; it < 8; it++) {
            int i   = tid + it * 256;
            int row = i >> 4;
            int sub = i & 15;
            int arr = sub >> 3;
            int ch  = sub & 7;
            int gr  = bm + row;
            if (gr < M) {
                const __nv_bfloat16* src =
                    (arr ? Al : Ah) + (size_t)gr * KTOT + k0 + ch * 8;
                cp16(base + arr * A_SZ + row * (ST * 2) + ch * 16, src);
            }
        }
#pragma unroll
        for (int it = 0; it < 4; it++) {
            int i   = tid + it * 256;
            int n   = i >> 4;
            int sub = i & 15;
            int arr = sub >> 3;
            int ch  = sub & 7;
            const __nv_bfloat16* src =
                (arr ? Bl : Bh) + (size_t)(bn + n) * KTOT + k0 + ch * 8;
            cp16(base + 2 * A_SZ + arr * B_SZ + n * (ST * 2) + ch * 16, src);
        }
        cp_commit();
    };

    load_stage(0, 0);

    for (int s = 0; s < NSTAGE; s++) {
        int buf = (PIPE == 2) ? (s & 1) : 0;
        if (PIPE == 2 && s + 1 < NSTAGE) load_stage(s + 1, buf ^ 1);
        if (PIPE == 2 && s + 1 < NSTAGE) cp_wait<1>(); else cp_wait<0>();
        __syncthreads();

        uint32_t bo = buf * STG;
#pragma unroll
        for (int ks = 0; ks < TK / 16; ks++) {
            uint32_t koff = bo + ks * 32;
            uint32_t ah0[4], ah1[4], al0[4], al1[4];
            uint32_t bh0[4], bh1[4], bl0[4], bl1[4];
            ldsm_x4(ah0, aAH[0] + koff);
            ldsm_x4(ah1, aAH[1] + koff);
            ldsm_x4(al0, aAL[0] + koff);
            ldsm_x4(al1, aAL[1] + koff);
            ldsm_x4(bh0, aBH[0] + koff);
            ldsm_x4(bh1, aBH[1] + koff);
            ldsm_x4(bl0, aBL[0] + koff);
            ldsm_x4(bl1, aBL[1] + koff);
#pragma unroll
            for (int mt = 0; mt < 2; mt++) {
                const uint32_t* a_h = mt ? ah1 : ah0;
                const uint32_t* a_l = mt ? al1 : al0;
#pragma unroll
                for (int nt = 0; nt < 4; nt++) {
                    const uint32_t* b_h = (nt >> 1) ? bh1 : bh0;
                    const uint32_t* b_l = (nt >> 1) ? bl1 : bl0;
                    int sub = nt & 1;
                    mma_bf16(acc[mt][nt], a_h, b_h[sub], b_h[sub + 2]);
                    mma_bf16(acc[mt][nt], a_h, b_l[sub], b_l[sub + 2]);
                    mma_bf16(acc[mt][nt], a_l, b_h[sub], b_h[sub + 2]);
                }
            }
        }
        __syncthreads();
    }

    int g = l >> 2, tg = l & 3;
#pragma unroll
    for (int mt = 0; mt < 2; mt++) {
        int row0 = bm + wm * 32 + mt * 16 + g;
        float zs0 = 0.f, zs1 = 0.f;
        if (ZINIT) {
            if (row0 < M)     { float d0 = g_dinv[row0];     zs0 = d0 * d0; }
            if (row0 + 8 < M) { float d1 = g_dinv[row0 + 8]; zs1 = d1 * d1; }
        }
#pragma unroll
        for (int nt = 0; nt < 4; nt++) {
            int col = bn + wn * 32 + nt * 8 + tg * 2;
            float bx = 0.f, by = 0.f;
            if (BIAS) {
                float2 bv = *(const float2*)&bias[col];
                bx = bv.x; by = bv.y;
            }
            float2 o0 = make_float2(acc[mt][nt][0] + bx, acc[mt][nt][1] + by);
            float2 o1 = make_float2(acc[mt][nt][2] + bx, acc[mt][nt][3] + by);
            if (RELU) {
                o0.x = fmaxf(o0.x, 0.f); o0.y = fmaxf(o0.y, 0.f);
                o1.x = fmaxf(o1.x, 0.f); o1.y = fmaxf(o1.y, 0.f);
            }
            if (SPLIT) {
                uint32_t lp;
                if (row0 < M) {
                    uint32_t hp = split_pack_hi(o0.x, o0.y, lp);
                    *(uint32_t*)&Ch[(size_t)row0 * NTOT + col] = hp;
                    *(uint32_t*)&Cl[(size_t)row0 * NTOT + col] = lp;
                }
                if (row0 + 8 < M) {
                    uint32_t hp = split_pack_hi(o1.x, o1.y, lp);
                    *(uint32_t*)&Ch[(size_t)(row0 + 8) * NTOT + col] = hp;
                    *(uint32_t*)&Cl[(size_t)(row0 + 8) * NTOT + col] = lp;
                }
            } else {
                if (row0 < M) {
                    *(float2*)&Cf[(size_t)row0 * NTOT + col] = o0;
                    if (ZINIT) {
                        float2 bz = *(const float2*)&bias[col];
                        float2 zi = make_float2(fmaf(o0.x, zs0, bz.x),
                                                fmaf(o0.y, zs0, bz.y));
                        *(float2*)&g_z[(size_t)row0 * NTOT + col] = zi;
                    }
                }
                if (row0 + 8 < M) {
                    *(float2*)&Cf[(size_t)(row0 + 8) * NTOT + col] = o1;
                    if (ZINIT) {
                        float2 bz = *(const float2*)&bias[col];
                        float2 zi = make_float2(fmaf(o1.x, zs1, bz.x),
                                                fmaf(o1.y, zs1, bz.y));
                        *(float2*)&g_z[(size_t)(row0 + 8) * NTOT + col] = zi;
                    }
                }
            }
        }
    }
}

// -------- init aggregation: agg[i] = h[i]/deg[i]; stores dinv --------------
template<int C>
__global__ void k_init_agg(const float* __restrict__ h, float* __restrict__ agg)
{
    const int V = C / 4;
    int idx = blockIdx.x * 256 + threadIdx.x;
    if (idx >= NN * V) return;
    int node = idx / V;
    int v    = idx % V;
    float di = rsqrtf(g_deg[node]);
    if (v == 0) g_dinv[node] = di;
    float s = di * di;
    float4 hv = ((const float4*)h)[(size_t)node * V + v];
    float4 o;
    o.x = hv.x * s; o.y = hv.y * s; o.z = hv.z * s; o.w = hv.w * s;
    ((float4*)agg)[(size_t)node * V + v] = o;
}

// ---------------- edge scatter: agg[dst] += h[src] * dinv[src]*dinv[dst] ---
template<int C, int LPE>
__global__ void k_scatter(const int* __restrict__ src, const int* __restrict__ dst,
                          const float* __restrict__ h, float* __restrict__ agg)
{
    const int V = C / 4;
    int t   = blockIdx.x * 256 + threadIdx.x;
    int e   = t / LPE;
    int sub = t % LPE;
    if (e >= ECNT) return;
    int s = src[e];
    int d = dst[e];
    float norm = g_dinv[s] * g_dinv[d];
    const float4* hp = (const float4*)h   + (size_t)s * V;
    float4*       ap = (float4*)agg       + (size_t)d * V;
#pragma unroll
    for (int v = sub; v < V; v += LPE) {
        float4 hv = hp[v];
        float mx = hv.x * norm, my = hv.y * norm, mz = hv.z * norm, mw = hv.w * norm;
        asm volatile("red.global.add.v4.f32 [%0], {%1, %2, %3, %4};"
                     :: "l"(ap + v), "f"(mx), "f"(my), "f"(mz), "f"(mw)
                     : "memory");
    }
}

// ---------------- launch ---------------------------------------------------
extern "C" void kernel_launch(void* const* d_in, const int* in_sizes, int n_in,
                              void* d_out, int out_size)
{
    const float* x   = (const float*)d_in[0];
    const int*   ei  = (const int*)  d_in[1];
    const float* W1  = (const float*)d_in[2];
    const float* b1  = (const float*)d_in[3];
    const float* W2  = (const float*)d_in[4];
    const float* b2  = (const float*)d_in[5];
    const float* Wd1 = (const float*)d_in[6];
    const float* bd1 = (const float*)d_in[7];
    const float* Wd2 = (const float*)d_in[8];
    const float* bd2 = (const float*)d_in[9];
    float* out = (float*)d_out;

    const int* srcp = ei;
    const int* dstp = ei + ECNT;

    float *p_aggx, *p_h2, *p_z;
    cudaGetSymbolAddress((void**)&p_aggx, g_aggx);
    cudaGetSymbolAddress((void**)&p_h2,   g_h2);
    cudaGetSymbolAddress((void**)&p_z,    g_z);
    __nv_bfloat16 *p_axh, *p_axl, *p_h1h, *p_h1l, *p_zh, *p_zl, *p_dh, *p_dl;
    __nv_bfloat16 *p_w1h, *p_w1l, *p_w2h, *p_w2l, *p_wd1h, *p_wd1l, *p_wd2h, *p_wd2l;
    cudaGetSymbolAddress((void**)&p_axh, g_axh);
    cudaGetSymbolAddress((void**)&p_axl, g_axl);
    cudaGetSymbolAddress((void**)&p_h1h, g_h1h);
    cudaGetSymbolAddress((void**)&p_h1l, g_h1l);
    cudaGetSymbolAddress((void**)&p_zh,  g_zh);
    cudaGetSymbolAddress((void**)&p_zl,  g_zl);
    cudaGetSymbolAddress((void**)&p_dh,  g_dh);
    cudaGetSymbolAddress((void**)&p_dl,  g_dl);
    cudaGetSymbolAddress((void**)&p_w1h, g_w1h);
    cudaGetSymbolAddress((void**)&p_w1l, g_w1l);
    cudaGetSymbolAddress((void**)&p_w2h, g_w2h);
    cudaGetSymbolAddress((void**)&p_w2l, g_w2l);
    cudaGetSymbolAddress((void**)&p_wd1h, g_wd1h);
    cudaGetSymbolAddress((void**)&p_wd1l, g_wd1l);
    cudaGetSymbolAddress((void**)&p_wd2h, g_wd2h);
    cudaGetSymbolAddress((void**)&p_wd2l, g_wd2l);

    const int STG = 2 * (128 * 72 * 2) + 2 * (64 * 72 * 2);  // 55296
    cudaFuncSetAttribute((const void*)k_gemm_bf<128, 256, true,  true,  true,  false>,
                         cudaFuncAttributeMaxDynamicSharedMemorySize, 2 * STG);
    cudaFuncSetAttribute((const void*)k_gemm_bf<256, 64,  false, false, false, true >,
                         cudaFuncAttributeMaxDynamicSharedMemorySize, 2 * STG);
    cudaFuncSetAttribute((const void*)k_gemm_bf<64,  256, true,  true,  true,  false>,
                         cudaFuncAttributeMaxDynamicSharedMemorySize, STG);
    cudaFuncSetAttribute((const void*)k_gemm_bf<256, 128, true,  false, false, false>,
                         cudaFuncAttributeMaxDynamicSharedMemorySize, 2 * STG);

    // --- prep (weight splits + deg init) + degree count
    k_prep<<<(98304 + NN + 255) / 256, 256>>>(W1, W2, Wd1, Wd2);
    k_deg_count<<<(ECNT + 255) / 256, 256>>>(dstp);

    const int MB = (NN + 127) / 128;   // 391 row-blocks

    // --- layer 1: aggx = Dsym-scatter(x); split; h1 = relu(aggx@W1+b1)
    k_init_agg<128><<<(NN * 32 + 255) / 256, 256>>>(x, p_aggx);
    k_scatter<128,32><<<(ECNT * 32) / 256, 256>>>(srcp, dstp, x, p_aggx);
    k_split<<<(NN * 32 + 255) / 256, 256>>>(p_aggx, p_axh, p_axl, NN * 32);
    k_gemm_bf<128, 256, true, true, true, false><<<dim3(4, MB), 256, 2 * STG>>>(
        p_axh, p_axl, p_w1h, p_w1l, b1, nullptr, p_h1h, p_h1l);

    // --- layer 2: h2 = h1 @ W2 [fp32, fused z-init]; scatter; split
    k_gemm_bf<256, 64, false, false, false, true><<<dim3(1, MB), 256, 2 * STG>>>(
        p_h1h, p_h1l, p_w2h, p_w2l, b2, p_h2, nullptr, nullptr);
    k_scatter<64,16><<<(ECNT * 16) / 256, 256>>>(srcp, dstp, p_h2, p_z);
    k_split<<<(NN * 16 + 255) / 256, 256>>>(p_z, p_zh, p_zl, NN * 16);

    // --- decoder: d = relu(z @ Wd1 + bd1); out = d @ Wd2 + bd2
    k_gemm_bf<64, 256, true, true, true, false><<<dim3(4, MB), 256, STG>>>(
        p_zh, p_zl, p_wd1h, p_wd1l, bd1, nullptr, p_dh, p_dl);
    k_gemm_bf<256, 128, true, false, false, false><<<dim3(2, MB), 256, 2 * STG>>>(
        p_dh, p_dl, p_wd2h, p_wd2l, bd2, out, nullptr, nullptr);
}